// round 3
// baseline (speedup 1.0000x reference)
#include <cuda_runtime.h>

#define BATCH 262144
#define TWO_PI_F 6.28318530717958647692f

static __device__ double g_acc;

__global__ void ciou_init_kernel() { g_acc = 0.0; }

__global__ void __launch_bounds__(128) ciou_main_kernel(
    const float* __restrict__ A, const float* __restrict__ Bm) {
  int i = blockIdx.x * blockDim.x + threadIdx.x;
  float ciou_v = 0.0f;
  if (i < BATCH) {
    const float INF_F = __int_as_float(0x7f800000);
    // ---------------- load originals (kept in registers for hull) ----------
    float oxa[8], oya[8], oxb[8], oyb[8];
    {
      const float4* a4 = reinterpret_cast<const float4*>(A) + (size_t)i * 4;
      const float4* b4 = reinterpret_cast<const float4*>(Bm) + (size_t)i * 4;
#pragma unroll
      for (int k = 0; k < 4; k++) {
        float4 q = a4[k];
        oxa[2 * k] = q.x; oya[2 * k] = q.y; oxa[2 * k + 1] = q.z; oya[2 * k + 1] = q.w;
      }
#pragma unroll
      for (int k = 0; k < 4; k++) {
        float4 q = b4[k];
        oxb[2 * k] = q.x; oyb[2 * k] = q.y; oxb[2 * k + 1] = q.z; oyb[2 * k + 1] = q.w;
      }
    }

    // ---------------- sort_poly (stable rank sort, register-resident) ------
    float sax[8], say[8], sbx[8], sby[8];
    {
      float cx = 0.f, cy = 0.f;
#pragma unroll
      for (int k = 0; k < 8; k++) { cx += oxa[k]; cy += oya[k]; }
      cx *= 0.125f; cy *= 0.125f;
      float ang[8];
#pragma unroll
      for (int k = 0; k < 8; k++) ang[k] = atan2f(oya[k] - cy, oxa[k] - cx);
      int rk[8];
#pragma unroll
      for (int j = 0; j < 8; j++) {
        int r = 0;
#pragma unroll
        for (int k = 0; k < 8; k++)
          r += (int)((ang[k] < ang[j]) || ((ang[k] == ang[j]) && (k < j)));
        rk[j] = r;
      }
#pragma unroll
      for (int s = 0; s < 8; s++) {
        float vx = 0.f, vy = 0.f;
#pragma unroll
        for (int j = 0; j < 8; j++) {
          bool sel = (rk[j] == s);
          vx = sel ? oxa[j] : vx;
          vy = sel ? oya[j] : vy;
        }
        sax[s] = vx; say[s] = vy;
      }
    }
    {
      float cx = 0.f, cy = 0.f;
#pragma unroll
      for (int k = 0; k < 8; k++) { cx += oxb[k]; cy += oyb[k]; }
      cx *= 0.125f; cy *= 0.125f;
      float ang[8];
#pragma unroll
      for (int k = 0; k < 8; k++) ang[k] = atan2f(oyb[k] - cy, oxb[k] - cx);
      int rk[8];
#pragma unroll
      for (int j = 0; j < 8; j++) {
        int r = 0;
#pragma unroll
        for (int k = 0; k < 8; k++)
          r += (int)((ang[k] < ang[j]) || ((ang[k] == ang[j]) && (k < j)));
        rk[j] = r;
      }
#pragma unroll
      for (int s = 0; s < 8; s++) {
        float vx = 0.f, vy = 0.f;
#pragma unroll
        for (int j = 0; j < 8; j++) {
          bool sel = (rk[j] == s);
          vx = sel ? oxb[j] : vx;
          vy = sel ? oyb[j] : vy;
        }
        sbx[s] = vx; sby[s] = vy;
      }
    }

    // ---------------- edges + shoelace areas -------------------------------
    float eax[8], eay[8], ebx[8], eby[8];
#pragma unroll
    for (int k = 0; k < 8; k++) {
      eax[k] = sax[(k + 1) & 7] - sax[k];
      eay[k] = say[(k + 1) & 7] - say[k];
      ebx[k] = sbx[(k + 1) & 7] - sbx[k];
      eby[k] = sby[(k + 1) & 7] - sby[k];
    }
    float area_a = 0.f, area_b = 0.f;
#pragma unroll
    for (int k = 0; k < 8; k++) {
      area_a += sax[k] * say[(k + 1) & 7] - say[k] * sax[(k + 1) & 7];
      area_b += sbx[k] * sby[(k + 1) & 7] - sby[k] * sbx[(k + 1) & 7];
    }
    area_a *= 0.5f; area_b *= 0.5f;

    // ---------------- candidates: inside vertices + edge intersections -----
    float cxl[80], cyl[80], cal[80];  // local-memory arrays (dynamic index)
    int cnt = 0;
    float sumx = 0.f, sumy = 0.f;

    // a-vertices inside b  (order: a first — matches reference concat order)
#pragma unroll
    for (int j = 0; j < 8; j++) {
      bool all = true;
#pragma unroll
      for (int k = 0; k < 8; k++) {
        float wx = sax[j] - sbx[k], wy = say[j] - sby[k];
        float cr = ebx[k] * wy - eby[k] * wx;
        all = all && (cr >= -1e-6f);
      }
      if (all) { cxl[cnt] = sax[j]; cyl[cnt] = say[j]; sumx += sax[j]; sumy += say[j]; cnt++; }
    }
    // b-vertices inside a
#pragma unroll
    for (int j = 0; j < 8; j++) {
      bool all = true;
#pragma unroll
      for (int k = 0; k < 8; k++) {
        float wx = sbx[j] - sax[k], wy = sby[j] - say[k];
        float cr = eax[k] * wy - eay[k] * wx;
        all = all && (cr >= -1e-6f);
      }
      if (all) { cxl[cnt] = sbx[j]; cyl[cnt] = sby[j]; sumx += sbx[j]; sumy += sby[j]; cnt++; }
    }
    // edge-edge intersections, i-major then j (reference reshape order)
#pragma unroll
    for (int ii = 0; ii < 8; ii++) {
#pragma unroll
      for (int jj = 0; jj < 8; jj++) {
        float denom = eax[ii] * eby[jj] - eay[ii] * ebx[jj];
        float ad = fabsf(denom);
        float safe = (ad < 1e-9f) ? 1.0f : denom;
        float rx = sbx[jj] - sax[ii], ry = sby[jj] - say[ii];
        float t = (rx * eby[jj] - ry * ebx[jj]) / safe;
        float u = (rx * eay[ii] - ry * eax[ii]) / safe;
        bool ok = (ad >= 1e-9f) && (t >= 0.0f) && (t <= 1.0f) && (u >= 0.0f) && (u <= 1.0f);
        if (ok) {
          float px = sax[ii] + t * eax[ii];
          float py = say[ii] + t * eay[ii];
          cxl[cnt] = px; cyl[cnt] = py; sumx += px; sumy += py; cnt++;
        }
      }
    }

    // ---------------- intersection area: angle sort about centroid ---------
    float inter = 0.0f;
    {
      float cntf = fmaxf((float)cnt, 1.0f);
      float ctrx = sumx / cntf, ctry = sumy / cntf;
      for (int t0 = 0; t0 < cnt; t0++)
        cal[t0] = atan2f(cyl[t0] - ctry, cxl[t0] - ctrx);
      // stable insertion sort of (angle, x, y)
      for (int s = 1; s < cnt; s++) {
        float ka = cal[s], kx = cxl[s], ky = cyl[s];
        int t = s - 1;
        while (t >= 0 && cal[t] > ka) {
          cal[t + 1] = cal[t]; cxl[t + 1] = cxl[t]; cyl[t + 1] = cyl[t];
          t--;
        }
        cal[t + 1] = ka; cxl[t + 1] = kx; cyl[t + 1] = ky;
      }
      float sh = 0.f;
      for (int t0 = 0; t0 < cnt; t0++) {
        int t1 = (t0 + 1 == cnt) ? 0 : t0 + 1;
        sh += cxl[t0] * cyl[t1] - cyl[t0] * cxl[t1];
      }
      inter = (cnt >= 3) ? fmaxf(0.5f * sh, 0.0f) : 0.0f;
    }

    float uni = area_a + area_b - inter;
    float iou = inter / uni;

    // ---------------- convex hull (gift wrapping) on the 16 raw points -----
    float ch;
    {
      // start = lexsort((x, y))[0]: min y, tie min x, tie min index
      int start = 0;
      float cpx = oxa[0], cpy = oya[0];
#pragma unroll
      for (int k = 1; k < 16; k++) {
        float pxk = (k < 8) ? oxa[k] : oxb[k - 8];
        float pyk = (k < 8) ? oya[k] : oyb[k - 8];
        bool better = (pyk < cpy) || ((pyk == cpy) && (pxk < cpx));
        if (better) { start = k; cpx = pxk; cpy = pyk; }
      }
      float dx = 1.0f, dy = 0.0f;
      float acc = 0.0f;
      for (int it = 0; it < 16; it++) {
        float best = INF_F;
        int nxt = 0;
        float nx = 0.f, ny = 0.f;
#pragma unroll
        for (int k = 0; k < 16; k++) {
          float pxk = (k < 8) ? oxa[k] : oxb[k - 8];
          float pyk = (k < 8) ? oya[k] : oyb[k - 8];
          float vx = pxk - cpx, vy = pyk - cpy;
          float d2 = vx * vx + vy * vy;
          float a = atan2f(dx * vy - dy * vx, dx * vx + dy * vy);
          if (a < 0.0f) a += TWO_PI_F;  // floor-mod into [0, 2pi)
          a = (d2 < 1e-16f) ? INF_F : a;
          if (a < best) { best = a; nxt = k; nx = pxk; ny = pyk; }
        }
        acc += cpx * ny - cpy * nx;  // done=false up to and including closure
        dx = nx - cpx; dy = ny - cpy;
        cpx = nx; cpy = ny;
        if (nxt == start) break;  // remaining reference iters add 0
      }
      ch = 0.5f * acc;
    }

    ciou_v = iou - (ch - uni) / ch;
  }

  // ---------------- mean reduction (double) --------------------------------
  double v = (double)ciou_v;
#pragma unroll
  for (int o = 16; o > 0; o >>= 1) v += __shfl_down_sync(0xFFFFFFFFu, v, o);
  __shared__ double smem[4];
  int lane = threadIdx.x & 31;
  int wid = threadIdx.x >> 5;
  if (lane == 0) smem[wid] = v;
  __syncthreads();
  if (threadIdx.x == 0) {
    double s = smem[0] + smem[1] + smem[2] + smem[3];
    atomicAdd(&g_acc, s);
  }
}

__global__ void ciou_fin_kernel(float* out) {
  out[0] = (float)(g_acc * (1.0 / (double)BATCH));
}

extern "C" void kernel_launch(void* const* d_in, const int* in_sizes, int n_in,
                              void* d_out, int out_size) {
  const float* a = (const float*)d_in[0];
  const float* b = (const float*)d_in[1];
  float* out = (float*)d_out;
  ciou_init_kernel<<<1, 1>>>();
  ciou_main_kernel<<<BATCH / 128, 128>>>(a, b);
  ciou_fin_kernel<<<1, 1>>>(out);
}

// round 4
// speedup vs baseline: 2.4528x; 2.4528x over previous
#include <cuda_runtime.h>

#define BATCH 262144
#define NBLOCKS (BATCH / 128)

static __device__ double g_acc = 0.0;
static __device__ unsigned int g_cnt = 0;

// Monotone key equivalent to atan2f(y, x) ordering over (-pi, pi].
// y>=0 (incl. -0): key = 1 - x/(|x|+|y|) in [0, 2]   (atan2 in [0, pi])
// y<0          : key = x/(|x|+|y|) - 1 in (-2, 0)    (atan2 in (-pi, 0))
// atan2(0,0)=0 -> key 0.
__device__ __forceinline__ float pangle(float x, float y) {
  float a = fabsf(x) + fabsf(y);
  float r = (a == 0.0f) ? 1.0f : __fdividef(x, a);
  return (y >= 0.0f) ? (1.0f - r) : (r - 1.0f);
}

// Monotone key equivalent to mod(atan2f(c, d), 2pi) ordering over [0, 2pi).
// c>=0 (incl. -0): key = 1 - d/(|c|+|d|) in [0, 2]
// c<0           : key = 3 + d/(|c|+|d|) in (2, 4)
__device__ __forceinline__ float pangle2pi(float c, float d) {
  float a = fabsf(c) + fabsf(d);
  float r = (a == 0.0f) ? 1.0f : __fdividef(d, a);
  return (c >= 0.0f) ? (1.0f - r) : (3.0f + r);
}

__global__ void __launch_bounds__(128) ciou_main_kernel(
    const float* __restrict__ A, const float* __restrict__ Bm,
    float* __restrict__ out) {
  int i = blockIdx.x * blockDim.x + threadIdx.x;
  const float INF_F = __int_as_float(0x7f800000);

  // ---------------- load originals (kept for hull) -------------------------
  float oxa[8], oya[8], oxb[8], oyb[8];
  {
    const float4* a4 = reinterpret_cast<const float4*>(A) + (size_t)i * 4;
    const float4* b4 = reinterpret_cast<const float4*>(Bm) + (size_t)i * 4;
#pragma unroll
    for (int k = 0; k < 4; k++) {
      float4 q = a4[k];
      oxa[2 * k] = q.x; oya[2 * k] = q.y; oxa[2 * k + 1] = q.z; oya[2 * k + 1] = q.w;
    }
#pragma unroll
    for (int k = 0; k < 4; k++) {
      float4 q = b4[k];
      oxb[2 * k] = q.x; oyb[2 * k] = q.y; oxb[2 * k + 1] = q.z; oyb[2 * k + 1] = q.w;
    }
  }

  // ---------------- sort_poly (stable rank sort, pseudoangle keys) ---------
  float sax[8], say[8], sbx[8], sby[8];
  {
    float cx = 0.f, cy = 0.f;
#pragma unroll
    for (int k = 0; k < 8; k++) { cx += oxa[k]; cy += oya[k]; }
    cx *= 0.125f; cy *= 0.125f;
    float ang[8];
#pragma unroll
    for (int k = 0; k < 8; k++) ang[k] = pangle(oxa[k] - cx, oya[k] - cy);
    int rk[8];
#pragma unroll
    for (int j = 0; j < 8; j++) {
      int r = 0;
#pragma unroll
      for (int k = 0; k < 8; k++)
        r += (int)((ang[k] < ang[j]) || ((ang[k] == ang[j]) && (k < j)));
      rk[j] = r;
    }
#pragma unroll
    for (int s = 0; s < 8; s++) {
      float vx = 0.f, vy = 0.f;
#pragma unroll
      for (int j = 0; j < 8; j++) {
        bool sel = (rk[j] == s);
        vx = sel ? oxa[j] : vx;
        vy = sel ? oya[j] : vy;
      }
      sax[s] = vx; say[s] = vy;
    }
  }
  {
    float cx = 0.f, cy = 0.f;
#pragma unroll
    for (int k = 0; k < 8; k++) { cx += oxb[k]; cy += oyb[k]; }
    cx *= 0.125f; cy *= 0.125f;
    float ang[8];
#pragma unroll
    for (int k = 0; k < 8; k++) ang[k] = pangle(oxb[k] - cx, oyb[k] - cy);
    int rk[8];
#pragma unroll
    for (int j = 0; j < 8; j++) {
      int r = 0;
#pragma unroll
      for (int k = 0; k < 8; k++)
        r += (int)((ang[k] < ang[j]) || ((ang[k] == ang[j]) && (k < j)));
      rk[j] = r;
    }
#pragma unroll
    for (int s = 0; s < 8; s++) {
      float vx = 0.f, vy = 0.f;
#pragma unroll
      for (int j = 0; j < 8; j++) {
        bool sel = (rk[j] == s);
        vx = sel ? oxb[j] : vx;
        vy = sel ? oyb[j] : vy;
      }
      sbx[s] = vx; sby[s] = vy;
    }
  }

  // ---------------- edges + shoelace areas ---------------------------------
  float eax[8], eay[8], ebx[8], eby[8];
#pragma unroll
  for (int k = 0; k < 8; k++) {
    eax[k] = sax[(k + 1) & 7] - sax[k];
    eay[k] = say[(k + 1) & 7] - say[k];
    ebx[k] = sbx[(k + 1) & 7] - sbx[k];
    eby[k] = sby[(k + 1) & 7] - sby[k];
  }
  float area_a = 0.f, area_b = 0.f;
#pragma unroll
  for (int k = 0; k < 8; k++) {
    area_a += sax[k] * say[(k + 1) & 7] - say[k] * sax[(k + 1) & 7];
    area_b += sbx[k] * sby[(k + 1) & 7] - sby[k] * sbx[(k + 1) & 7];
  }
  area_a *= 0.5f; area_b *= 0.5f;

  // ---------------- candidates: inside vertices + edge intersections -------
  float cxl[80], cyl[80], cal[80];
  int cnt = 0;
  float sumx = 0.f, sumy = 0.f;

#pragma unroll
  for (int j = 0; j < 8; j++) {
    bool all = true;
#pragma unroll
    for (int k = 0; k < 8; k++) {
      float wx = sax[j] - sbx[k], wy = say[j] - sby[k];
      float cr = ebx[k] * wy - eby[k] * wx;
      all = all && (cr >= -1e-6f);
    }
    if (all) { cxl[cnt] = sax[j]; cyl[cnt] = say[j]; sumx += sax[j]; sumy += say[j]; cnt++; }
  }
#pragma unroll
  for (int j = 0; j < 8; j++) {
    bool all = true;
#pragma unroll
    for (int k = 0; k < 8; k++) {
      float wx = sbx[j] - sax[k], wy = sby[j] - say[k];
      float cr = eax[k] * wy - eay[k] * wx;
      all = all && (cr >= -1e-6f);
    }
    if (all) { cxl[cnt] = sbx[j]; cyl[cnt] = sby[j]; sumx += sbx[j]; sumy += sby[j]; cnt++; }
  }
#pragma unroll
  for (int ii = 0; ii < 8; ii++) {
#pragma unroll
    for (int jj = 0; jj < 8; jj++) {
      float denom = eax[ii] * eby[jj] - eay[ii] * ebx[jj];
      float ad = fabsf(denom);
      float inv = __fdividef(1.0f, (ad < 1e-9f) ? 1.0f : denom);
      float rx = sbx[jj] - sax[ii], ry = sby[jj] - say[ii];
      float t = (rx * eby[jj] - ry * ebx[jj]) * inv;
      float u = (rx * eay[ii] - ry * eax[ii]) * inv;
      bool ok = (ad >= 1e-9f) && (t >= 0.0f) && (t <= 1.0f) && (u >= 0.0f) && (u <= 1.0f);
      if (ok) {
        float px = sax[ii] + t * eax[ii];
        float py = say[ii] + t * eay[ii];
        cxl[cnt] = px; cyl[cnt] = py; sumx += px; sumy += py; cnt++;
      }
    }
  }

  // ---------------- intersection area: pseudoangle sort about centroid -----
  float inter = 0.0f;
  {
    float cntf = fmaxf((float)cnt, 1.0f);
    float ctrx = sumx / cntf, ctry = sumy / cntf;
    for (int t0 = 0; t0 < cnt; t0++)
      cal[t0] = pangle(cxl[t0] - ctrx, cyl[t0] - ctry);
    for (int s = 1; s < cnt; s++) {
      float ka = cal[s], kx = cxl[s], ky = cyl[s];
      int t = s - 1;
      while (t >= 0 && cal[t] > ka) {
        cal[t + 1] = cal[t]; cxl[t + 1] = cxl[t]; cyl[t + 1] = cyl[t];
        t--;
      }
      cal[t + 1] = ka; cxl[t + 1] = kx; cyl[t + 1] = ky;
    }
    float sh = 0.f;
    for (int t0 = 0; t0 < cnt; t0++) {
      int t1 = (t0 + 1 == cnt) ? 0 : t0 + 1;
      sh += cxl[t0] * cyl[t1] - cyl[t0] * cxl[t1];
    }
    inter = (cnt >= 3) ? fmaxf(0.5f * sh, 0.0f) : 0.0f;
  }

  float uni = area_a + area_b - inter;
  float iou = inter / uni;

  // ---------------- convex hull (gift wrapping, pseudoangle) ---------------
  float ch;
  {
    int start = 0;
    float cpx = oxa[0], cpy = oya[0];
#pragma unroll
    for (int k = 1; k < 16; k++) {
      float pxk = (k < 8) ? oxa[k] : oxb[k - 8];
      float pyk = (k < 8) ? oya[k] : oyb[k - 8];
      bool better = (pyk < cpy) || ((pyk == cpy) && (pxk < cpx));
      if (better) { start = k; cpx = pxk; cpy = pyk; }
    }
    float dx = 1.0f, dy = 0.0f;
    float acc = 0.0f;
    for (int it = 0; it < 16; it++) {
      float best = INF_F;
      int nxt = 0;
      float nx = 0.f, ny = 0.f;
#pragma unroll
      for (int k = 0; k < 16; k++) {
        float pxk = (k < 8) ? oxa[k] : oxb[k - 8];
        float pyk = (k < 8) ? oya[k] : oyb[k - 8];
        float vx = pxk - cpx, vy = pyk - cpy;
        float d2 = vx * vx + vy * vy;
        float c = dx * vy - dy * vx;
        float d = dx * vx + dy * vy;
        float a = pangle2pi(c, d);
        a = (d2 < 1e-16f) ? INF_F : a;
        if (a < best) { best = a; nxt = k; nx = pxk; ny = pyk; }
      }
      acc += cpx * ny - cpy * nx;
      dx = nx - cpx; dy = ny - cpy;
      cpx = nx; cpy = ny;
      if (nxt == start) break;
    }
    ch = 0.5f * acc;
  }

  float ciou_v = iou - (ch - uni) / ch;

  // ---------------- mean reduction (double, single-kernel finalize) --------
  double v = (double)ciou_v;
#pragma unroll
  for (int o = 16; o > 0; o >>= 1) v += __shfl_down_sync(0xFFFFFFFFu, v, o);
  __shared__ double smem[4];
  int lane = threadIdx.x & 31;
  int wid = threadIdx.x >> 5;
  if (lane == 0) smem[wid] = v;
  __syncthreads();
  if (threadIdx.x == 0) {
    double s = smem[0] + smem[1] + smem[2] + smem[3];
    atomicAdd(&g_acc, s);
    __threadfence();
    unsigned int old = atomicAdd(&g_cnt, 1u);
    if (old == (unsigned int)(NBLOCKS - 1)) {
      double total = atomicAdd(&g_acc, 0.0);  // coherent read after all adds
      out[0] = (float)(total * (1.0 / (double)BATCH));
      g_acc = 0.0;   // reset for next (deterministic) replay
      g_cnt = 0u;
    }
  }
}

extern "C" void kernel_launch(void* const* d_in, const int* in_sizes, int n_in,
                              void* d_out, int out_size) {
  const float* a = (const float*)d_in[0];
  const float* b = (const float*)d_in[1];
  float* out = (float*)d_out;
  ciou_main_kernel<<<NBLOCKS, 128>>>(a, b, out);
}